// round 2
// baseline (speedup 1.0000x reference)
#include <cuda_runtime.h>
#include <math.h>

#define DIM   768
#define HEADS 16
#define DK    48
#define B     2
#define S     2048
#define MROWS (B * S)          // 4096

// Scratch (static device globals — no runtime allocation)
__device__ float g_q[B * HEADS * S * DK];
__device__ float g_k[B * HEADS * S * DK];
__device__ float g_v[B * HEADS * S * DK];
__device__ float g_ctx[MROWS * DIM];

// ---------------------------------------------------------------------------
// Tiled SGEMM: out = A[M,K] @ W[N,K]^T + bias[N]
// MODE 0: out is [M,N] row-major
// MODE 1: out scattered to [B, HEADS, S, DK]  (m -> (b,s), n -> (h,d))
// Tile: BM=BN=64, BK=16, 256 threads, 4x4 microtile, double-buffered smem.
// ---------------------------------------------------------------------------
template <int MODE>
__global__ __launch_bounds__(256)
void gemm_bias_kernel(const float* __restrict__ A,
                      const float* __restrict__ W,
                      const float* __restrict__ bias,
                      float* __restrict__ out,
                      int M, int N, int K)
{
    __shared__ float As[2][16][64];
    __shared__ float Bs[2][16][64];

    const int tid = threadIdx.x;
    const int bm  = blockIdx.y * 64;
    const int bn  = blockIdx.x * 64;
    const int ty  = tid >> 4;          // 0..15
    const int tx  = tid & 15;          // 0..15

    // load mapping: 64 rows x 4 float4 columns
    const int lr = tid >> 2;           // 0..63 row within tile
    const int lk = (tid & 3) * 4;      // 0,4,8,12 k-offset

    float c[4][4];
    #pragma unroll
    for (int i = 0; i < 4; i++)
        #pragma unroll
        for (int j = 0; j < 4; j++) c[i][j] = 0.0f;

    const float* Aptr = A + (size_t)(bm + lr) * K + lk;
    const float* Wptr = W + (size_t)(bn + lr) * K + lk;

    // prologue: load first slab
    float4 av = *(const float4*)(Aptr);
    float4 wv = *(const float4*)(Wptr);
    As[0][lk + 0][lr] = av.x; As[0][lk + 1][lr] = av.y;
    As[0][lk + 2][lr] = av.z; As[0][lk + 3][lr] = av.w;
    Bs[0][lk + 0][lr] = wv.x; Bs[0][lk + 1][lr] = wv.y;
    Bs[0][lk + 2][lr] = wv.z; Bs[0][lk + 3][lr] = wv.w;
    __syncthreads();

    int buf = 0;
    for (int k0 = 16; k0 < K; k0 += 16) {
        // prefetch next slab into registers
        float4 av2 = *(const float4*)(Aptr + k0);
        float4 wv2 = *(const float4*)(Wptr + k0);

        // compute on current buffer
        #pragma unroll
        for (int kk = 0; kk < 16; kk++) {
            float4 a = *(const float4*)&As[buf][kk][ty * 4];
            float4 b = *(const float4*)&Bs[buf][kk][tx * 4];
            float ar[4] = {a.x, a.y, a.z, a.w};
            float br[4] = {b.x, b.y, b.z, b.w};
            #pragma unroll
            for (int i = 0; i < 4; i++)
                #pragma unroll
                for (int j = 0; j < 4; j++)
                    c[i][j] = fmaf(ar[i], br[j], c[i][j]);
        }

        buf ^= 1;
        As[buf][lk + 0][lr] = av2.x; As[buf][lk + 1][lr] = av2.y;
        As[buf][lk + 2][lr] = av2.z; As[buf][lk + 3][lr] = av2.w;
        Bs[buf][lk + 0][lr] = wv2.x; Bs[buf][lk + 1][lr] = wv2.y;
        Bs[buf][lk + 2][lr] = wv2.z; Bs[buf][lk + 3][lr] = wv2.w;
        __syncthreads();
    }

    // epilogue compute on last buffer
    #pragma unroll
    for (int kk = 0; kk < 16; kk++) {
        float4 a = *(const float4*)&As[buf][kk][ty * 4];
        float4 b = *(const float4*)&Bs[buf][kk][tx * 4];
        float ar[4] = {a.x, a.y, a.z, a.w};
        float br[4] = {b.x, b.y, b.z, b.w};
        #pragma unroll
        for (int i = 0; i < 4; i++)
            #pragma unroll
            for (int j = 0; j < 4; j++)
                c[i][j] = fmaf(ar[i], br[j], c[i][j]);
    }

    #pragma unroll
    for (int i = 0; i < 4; i++) {
        const int m = bm + ty * 4 + i;
        #pragma unroll
        for (int j = 0; j < 4; j++) {
            const int n = bn + tx * 4 + j;
            const float v = c[i][j] + bias[n];
            if (MODE == 0) {
                out[(size_t)m * N + n] = v;
            } else {
                const int bidx = m / S;
                const int s    = m % S;
                const int h    = n / DK;
                const int d    = n % DK;
                out[(((size_t)bidx * HEADS + h) * S + s) * DK + d] = v;
            }
        }
    }
}

// ---------------------------------------------------------------------------
// Flash attention: one thread owns one query row.
// Block = 128 threads = 128 query rows. K/V staged 64 keys at a time in smem.
// All smem traffic is float4 (LDS.128) to keep the FMA pipe the binding pipe.
// Online softmax with rescale-on-new-max.
// Writes ctx in [B, S, DIM] layout (heads re-interleaved).
// ---------------------------------------------------------------------------
#define KT 64                      // keys per smem tile
#define DK4 (DK / 4)               // 12 float4 per row

__global__ __launch_bounds__(128)
void attention_kernel(const float* __restrict__ Q,
                      const float* __restrict__ K,
                      const float* __restrict__ V,
                      float* __restrict__ ctx)
{
    const int qt = blockIdx.x;     // query tile: 0..15
    const int h  = blockIdx.y;     // head
    const int b  = blockIdx.z;     // batch
    const int t  = threadIdx.x;    // 0..127 -> query row within tile

    __shared__ float4 Ks[KT * DK4];
    __shared__ float4 Vs[KT * DK4];

    const size_t head_off = ((size_t)b * HEADS + h) * S * DK;
    const float scale = rsqrtf((float)DK);

    // q row into registers (pre-scaled)
    float qreg[DK];
    {
        const float4* qrow = (const float4*)(Q + head_off + (size_t)(qt * 128 + t) * DK);
        #pragma unroll
        for (int d4 = 0; d4 < DK4; d4++) {
            float4 qv = qrow[d4];
            qreg[d4 * 4 + 0] = qv.x * scale;
            qreg[d4 * 4 + 1] = qv.y * scale;
            qreg[d4 * 4 + 2] = qv.z * scale;
            qreg[d4 * 4 + 3] = qv.w * scale;
        }
    }

    float acc[DK];
    #pragma unroll
    for (int d = 0; d < DK; d++) acc[d] = 0.0f;
    float mrun = -INFINITY;
    float lrun = 0.0f;

    const float4* kbase = (const float4*)(K + head_off);
    const float4* vbase = (const float4*)(V + head_off);

    for (int kt = 0; kt < S; kt += KT) {
        // cooperative coalesced float4 load of KT keys + KT values
        const float4* ksrc = kbase + (size_t)kt * DK4;
        const float4* vsrc = vbase + (size_t)kt * DK4;
        #pragma unroll
        for (int i = t; i < KT * DK4; i += 128) {
            Ks[i] = ksrc[i];
            Vs[i] = vsrc[i];
        }
        __syncthreads();

        #pragma unroll 2
        for (int j = 0; j < KT; j++) {
            float s = 0.0f;
            #pragma unroll
            for (int d4 = 0; d4 < DK4; d4++) {
                float4 kv = Ks[j * DK4 + d4];
                s = fmaf(qreg[d4 * 4 + 0], kv.x, s);
                s = fmaf(qreg[d4 * 4 + 1], kv.y, s);
                s = fmaf(qreg[d4 * 4 + 2], kv.z, s);
                s = fmaf(qreg[d4 * 4 + 3], kv.w, s);
            }

            if (s > mrun) {
                const float corr = __expf(mrun - s);  // exp(-inf)=0 on first key
                lrun *= corr;
                #pragma unroll
                for (int d = 0; d < DK; d++) acc[d] *= corr;
                mrun = s;
            }
            const float p = __expf(s - mrun);
            lrun += p;
            #pragma unroll
            for (int d4 = 0; d4 < DK4; d4++) {
                float4 vv = Vs[j * DK4 + d4];
                acc[d4 * 4 + 0] = fmaf(p, vv.x, acc[d4 * 4 + 0]);
                acc[d4 * 4 + 1] = fmaf(p, vv.y, acc[d4 * 4 + 1]);
                acc[d4 * 4 + 2] = fmaf(p, vv.z, acc[d4 * 4 + 2]);
                acc[d4 * 4 + 3] = fmaf(p, vv.w, acc[d4 * 4 + 3]);
            }
        }
        __syncthreads();
    }

    const float inv = 1.0f / lrun;
    float4* orow = (float4*)(ctx + ((size_t)b * S + qt * 128 + t) * DIM + h * DK);
    #pragma unroll
    for (int d4 = 0; d4 < DK4; d4++) {
        float4 o;
        o.x = acc[d4 * 4 + 0] * inv;
        o.y = acc[d4 * 4 + 1] * inv;
        o.z = acc[d4 * 4 + 2] * inv;
        o.w = acc[d4 * 4 + 3] * inv;
        orow[d4] = o;
    }
}

// ---------------------------------------------------------------------------
extern "C" void kernel_launch(void* const* d_in, const int* in_sizes, int n_in,
                              void* d_out, int out_size)
{
    const float* x  = (const float*)d_in[0];
    const float* Wq = (const float*)d_in[1];
    const float* bq = (const float*)d_in[2];
    const float* Wk = (const float*)d_in[3];
    const float* bk = (const float*)d_in[4];
    const float* Wv = (const float*)d_in[5];
    const float* bv = (const float*)d_in[6];
    const float* Wo = (const float*)d_in[7];
    const float* bo = (const float*)d_in[8];
    float* out = (float*)d_out;

    float *q, *k, *v, *ctx;
    cudaGetSymbolAddress((void**)&q,   g_q);
    cudaGetSymbolAddress((void**)&k,   g_k);
    cudaGetSymbolAddress((void**)&v,   g_v);
    cudaGetSymbolAddress((void**)&ctx, g_ctx);

    dim3 gblk(256);
    dim3 ggrd(DIM / 64, MROWS / 64);   // (12, 64)

    // Q/K/V projections with fused head-layout scatter
    gemm_bias_kernel<1><<<ggrd, gblk>>>(x, Wq, bq, q, MROWS, DIM, DIM);
    gemm_bias_kernel<1><<<ggrd, gblk>>>(x, Wk, bk, k, MROWS, DIM, DIM);
    gemm_bias_kernel<1><<<ggrd, gblk>>>(x, Wv, bv, v, MROWS, DIM, DIM);

    // Attention
    dim3 agrd(S / 128, HEADS, B);      // (16, 16, 2)
    attention_kernel<<<agrd, 128>>>(q, k, v, ctx);

    // Output projection
    gemm_bias_kernel<0><<<ggrd, gblk>>>(ctx, Wo, bo, out, MROWS, DIM, DIM);
}

// round 3
// speedup vs baseline: 1.4333x; 1.4333x over previous
#include <cuda_runtime.h>
#include <math.h>
#include <stdint.h>

#define DIM   768
#define HEADS 16
#define DK    48
#define B     2
#define S     2048
#define MROWS (B * S)          // 4096

// Scratch (static device globals — no runtime allocation)
__device__ float g_q[B * HEADS * S * DK];
__device__ float g_k[B * HEADS * S * DK];
__device__ float g_v[B * HEADS * S * DK];
__device__ float g_ctx[MROWS * DIM];

// ---------------------------------------------------------------------------
// tf32 helpers
// ---------------------------------------------------------------------------
__device__ __forceinline__ uint32_t f2tf32(float f) {
    uint32_t r;
    asm("cvt.rna.tf32.f32 %0, %1;" : "=r"(r) : "f"(f));
    return r;
}

__device__ __forceinline__ void mma_tf32(float c[4],
                                         const uint32_t a[4],
                                         const uint32_t b[2]) {
    asm volatile(
        "mma.sync.aligned.m16n8k8.row.col.f32.tf32.tf32.f32 "
        "{%0,%1,%2,%3}, {%4,%5,%6,%7}, {%8,%9}, {%0,%1,%2,%3};\n"
        : "+f"(c[0]), "+f"(c[1]), "+f"(c[2]), "+f"(c[3])
        : "r"(a[0]), "r"(a[1]), "r"(a[2]), "r"(a[3]),
          "r"(b[0]), "r"(b[1]));
}

// ---------------------------------------------------------------------------
// Tensor-core GEMM: out = A[M,K] @ W[N,K]^T + bias[N]   (tf32 in, fp32 accum)
// Block tile 128x64, BK=32, 256 threads = 8 warps as 4x2 (warp tile 32x32).
// Each warp: 2 m-tiles (m16) x 4 n-tiles (n8), k in steps of 8.
// MODE 0: out [M,N] row-major.   MODE 1: scatter to [B,HEADS,S,DK].
// Dynamic smem, padded row stride 36 words (conflict-free fragment loads).
// ---------------------------------------------------------------------------
#define BK 32
#define APITCH 36
#define A_WORDS (128 * APITCH)       // per buffer
#define B_WORDS (64 * APITCH)
#define SMEM_WORDS (2 * (A_WORDS + B_WORDS))

template <int MODE>
__global__ __launch_bounds__(256)
void gemm_tc_kernel(const float* __restrict__ A,
                    const float* __restrict__ W,
                    const float* __restrict__ bias,
                    float* __restrict__ out,
                    int M, int N, int K)
{
    extern __shared__ uint32_t smem[];
    uint32_t* As = smem;                     // [2][128][36]
    uint32_t* Bs = smem + 2 * A_WORDS;       // [2][64][36]

    const int tid  = threadIdx.x;
    const int lane = tid & 31;
    const int warp = tid >> 5;
    const int warpM = warp >> 1;             // 0..3
    const int warpN = warp & 1;              // 0..1
    const int g   = lane >> 2;               // group id 0..7
    const int tig = lane & 3;                // thread in group 0..3

    const int bm = blockIdx.y * 128;
    const int bn = blockIdx.x * 64;

    // gmem load mapping
    const int lrA = tid >> 1;                // 0..127
    const int lkA = (tid & 1) * 16;          // 0 / 16
    const int lrB = tid >> 2;                // 0..63
    const int lkB = (tid & 3) * 8;           // 0/8/16/24

    const float* Aptr = A + (size_t)(bm + lrA) * K + lkA;
    const float* Wptr = W + (size_t)(bn + lrB) * K + lkB;

    float c[2][4][4];
    #pragma unroll
    for (int mt = 0; mt < 2; mt++)
        #pragma unroll
        for (int nt = 0; nt < 4; nt++)
            #pragma unroll
            for (int i = 0; i < 4; i++) c[mt][nt][i] = 0.0f;

    // ---- prologue: load first slab ----
    {
        #pragma unroll
        for (int i = 0; i < 4; i++) {
            float4 v = *(const float4*)(Aptr + i * 4);
            uint4 u = { f2tf32(v.x), f2tf32(v.y), f2tf32(v.z), f2tf32(v.w) };
            *(uint4*)&As[lrA * APITCH + lkA + i * 4] = u;
        }
        #pragma unroll
        for (int i = 0; i < 2; i++) {
            float4 v = *(const float4*)(Wptr + i * 4);
            uint4 u = { f2tf32(v.x), f2tf32(v.y), f2tf32(v.z), f2tf32(v.w) };
            *(uint4*)&Bs[lrB * APITCH + lkB + i * 4] = u;
        }
    }
    __syncthreads();

    int buf = 0;
    const int arow = warpM * 32;             // warp's A row base within tile
    const int bcol = warpN * 32;             // warp's B col base within tile

    for (int k0 = BK; k0 <= K; k0 += BK) {
        // prefetch next slab into registers (skip on last iter)
        float4 pa[4], pw[2];
        const bool more = (k0 < K);
        if (more) {
            #pragma unroll
            for (int i = 0; i < 4; i++) pa[i] = *(const float4*)(Aptr + k0 + i * 4);
            #pragma unroll
            for (int i = 0; i < 2; i++) pw[i] = *(const float4*)(Wptr + k0 + i * 4);
        }

        // compute on current buffer: 4 k-steps of 8
        const uint32_t* Ab = As + buf * A_WORDS;
        const uint32_t* Bb = Bs + buf * B_WORDS;
        #pragma unroll
        for (int ks = 0; ks < 4; ks++) {
            const int kc = ks * 8;
            uint32_t afr[2][4], bfr[4][2];
            #pragma unroll
            for (int mt = 0; mt < 2; mt++) {
                const int r0 = arow + mt * 16;
                afr[mt][0] = Ab[(r0 + g)     * APITCH + kc + tig];
                afr[mt][1] = Ab[(r0 + g + 8) * APITCH + kc + tig];
                afr[mt][2] = Ab[(r0 + g)     * APITCH + kc + tig + 4];
                afr[mt][3] = Ab[(r0 + g + 8) * APITCH + kc + tig + 4];
            }
            #pragma unroll
            for (int nt = 0; nt < 4; nt++) {
                const int n = bcol + nt * 8 + g;
                bfr[nt][0] = Bb[n * APITCH + kc + tig];
                bfr[nt][1] = Bb[n * APITCH + kc + tig + 4];
            }
            #pragma unroll
            for (int mt = 0; mt < 2; mt++)
                #pragma unroll
                for (int nt = 0; nt < 4; nt++)
                    mma_tf32(c[mt][nt], afr[mt], bfr[nt]);
        }

        if (more) {
            buf ^= 1;
            uint32_t* Aw = As + buf * A_WORDS;
            uint32_t* Bw = Bs + buf * B_WORDS;
            __syncthreads();   // ensure previous-buffer readers done before overwrite? (distinct buffers; sync for write->read ordering below)
            #pragma unroll
            for (int i = 0; i < 4; i++) {
                uint4 u = { f2tf32(pa[i].x), f2tf32(pa[i].y), f2tf32(pa[i].z), f2tf32(pa[i].w) };
                *(uint4*)&Aw[lrA * APITCH + lkA + i * 4] = u;
            }
            #pragma unroll
            for (int i = 0; i < 2; i++) {
                uint4 u = { f2tf32(pw[i].x), f2tf32(pw[i].y), f2tf32(pw[i].z), f2tf32(pw[i].w) };
                *(uint4*)&Bw[lrB * APITCH + lkB + i * 4] = u;
            }
            __syncthreads();
        }
    }

    // ---- epilogue ----
    #pragma unroll
    for (int mt = 0; mt < 2; mt++) {
        #pragma unroll
        for (int nt = 0; nt < 4; nt++) {
            #pragma unroll
            for (int i = 0; i < 4; i++) {
                const int m = bm + arow + mt * 16 + g + (i >> 1) * 8;
                const int n = bn + bcol + nt * 8 + 2 * tig + (i & 1);
                const float v = c[mt][nt][i] + bias[n];
                if (MODE == 0) {
                    out[(size_t)m * N + n] = v;
                } else {
                    const int bidx = m / S;
                    const int s    = m % S;
                    const int h    = n / DK;
                    const int d    = n % DK;
                    out[(((size_t)bidx * HEADS + h) * S + s) * DK + d] = v;
                }
            }
        }
    }
}

// ---------------------------------------------------------------------------
// Flash attention (round-1 version, measured 907us): one thread = one query.
// Block = 128 threads = 128 query rows. K/V staged 32 keys per smem tile.
// ---------------------------------------------------------------------------
__global__ __launch_bounds__(128)
void attention_kernel(const float* __restrict__ Q,
                      const float* __restrict__ K,
                      const float* __restrict__ V,
                      float* __restrict__ ctx)
{
    const int qt = blockIdx.x;
    const int h  = blockIdx.y;
    const int b  = blockIdx.z;
    const int t  = threadIdx.x;

    __shared__ float Ks[32 * DK];
    __shared__ float Vs[32 * DK];

    const size_t head_off = ((size_t)b * HEADS + h) * S * DK;
    const float scale = rsqrtf((float)DK);

    float qreg[DK];
    const float* qrow = Q + head_off + (size_t)(qt * 128 + t) * DK;
    #pragma unroll
    for (int d = 0; d < DK; d++) qreg[d] = qrow[d] * scale;

    float acc[DK];
    #pragma unroll
    for (int d = 0; d < DK; d++) acc[d] = 0.0f;
    float mrun = -INFINITY;
    float lrun = 0.0f;

    const float* kbase = K + head_off;
    const float* vbase = V + head_off;

    for (int kt = 0; kt < S; kt += 32) {
        #pragma unroll
        for (int i = t; i < 32 * DK; i += 128) {
            Ks[i] = kbase[(size_t)kt * DK + i];
            Vs[i] = vbase[(size_t)kt * DK + i];
        }
        __syncthreads();

        #pragma unroll 4
        for (int j = 0; j < 32; j++) {
            float s = 0.0f;
            #pragma unroll
            for (int d = 0; d < DK; d++)
                s = fmaf(qreg[d], Ks[j * DK + d], s);

            if (s > mrun) {
                const float corr = __expf(mrun - s);
                lrun *= corr;
                #pragma unroll
                for (int d = 0; d < DK; d++) acc[d] *= corr;
                mrun = s;
            }
            const float p = __expf(s - mrun);
            lrun += p;
            #pragma unroll
            for (int d = 0; d < DK; d++)
                acc[d] = fmaf(p, Vs[j * DK + d], acc[d]);
        }
        __syncthreads();
    }

    const float inv = 1.0f / lrun;
    float* orow = ctx + ((size_t)b * S + qt * 128 + t) * DIM + h * DK;
    #pragma unroll
    for (int d = 0; d < DK; d++) orow[d] = acc[d] * inv;
}

// ---------------------------------------------------------------------------
extern "C" void kernel_launch(void* const* d_in, const int* in_sizes, int n_in,
                              void* d_out, int out_size)
{
    const float* x  = (const float*)d_in[0];
    const float* Wq = (const float*)d_in[1];
    const float* bq = (const float*)d_in[2];
    const float* Wk = (const float*)d_in[3];
    const float* bk = (const float*)d_in[4];
    const float* Wv = (const float*)d_in[5];
    const float* bv = (const float*)d_in[6];
    const float* Wo = (const float*)d_in[7];
    const float* bo = (const float*)d_in[8];
    float* out = (float*)d_out;

    float *q, *k, *v, *ctx;
    cudaGetSymbolAddress((void**)&q,   g_q);
    cudaGetSymbolAddress((void**)&k,   g_k);
    cudaGetSymbolAddress((void**)&v,   g_v);
    cudaGetSymbolAddress((void**)&ctx, g_ctx);

    const int smem_bytes = SMEM_WORDS * 4;   // 55296
    cudaFuncSetAttribute(gemm_tc_kernel<0>,
                         cudaFuncAttributeMaxDynamicSharedMemorySize, smem_bytes);
    cudaFuncSetAttribute(gemm_tc_kernel<1>,
                         cudaFuncAttributeMaxDynamicSharedMemorySize, smem_bytes);

    dim3 gblk(256);
    dim3 ggrd(DIM / 64, MROWS / 128);   // (12, 32)

    gemm_tc_kernel<1><<<ggrd, gblk, smem_bytes>>>(x, Wq, bq, q, MROWS, DIM, DIM);
    gemm_tc_kernel<1><<<ggrd, gblk, smem_bytes>>>(x, Wk, bk, k, MROWS, DIM, DIM);
    gemm_tc_kernel<1><<<ggrd, gblk, smem_bytes>>>(x, Wv, bv, v, MROWS, DIM, DIM);

    dim3 agrd(S / 128, HEADS, B);       // (16, 16, 2)
    attention_kernel<<<agrd, 128>>>(q, k, v, ctx);

    gemm_tc_kernel<0><<<ggrd, gblk, smem_bytes>>>(ctx, Wo, bo, out, MROWS, DIM, DIM);
}

// round 4
// speedup vs baseline: 3.4759x; 2.4251x over previous
#include <cuda_runtime.h>
#include <math.h>
#include <stdint.h>

#define DIM   768
#define HEADS 16
#define DK    48
#define B     2
#define S     2048
#define MROWS (B * S)          // 4096

// Scratch (static device globals — no runtime allocation)
__device__ float g_q[B * HEADS * S * DK];
__device__ float g_k[B * HEADS * S * DK];
__device__ float g_v[B * HEADS * S * DK];
__device__ float g_ctx[MROWS * DIM];

// ---------------------------------------------------------------------------
// tf32 helpers
// ---------------------------------------------------------------------------
__device__ __forceinline__ uint32_t f2tf32(float f) {
    uint32_t r;
    asm("cvt.rna.tf32.f32 %0, %1;" : "=r"(r) : "f"(f));
    return r;
}

__device__ __forceinline__ void mma_tf32(float c[4],
                                         const uint32_t a[4],
                                         const uint32_t b[2]) {
    asm volatile(
        "mma.sync.aligned.m16n8k8.row.col.f32.tf32.tf32.f32 "
        "{%0,%1,%2,%3}, {%4,%5,%6,%7}, {%8,%9}, {%0,%1,%2,%3};\n"
        : "+f"(c[0]), "+f"(c[1]), "+f"(c[2]), "+f"(c[3])
        : "r"(a[0]), "r"(a[1]), "r"(a[2]), "r"(a[3]),
          "r"(b[0]), "r"(b[1]));
}

// ---------------------------------------------------------------------------
// Tensor-core GEMM: out = A[M,K] @ W[N,K]^T + bias[N]   (tf32 in, fp32 accum)
// (unchanged from round 3 — measured ~66us per GEMM)
// ---------------------------------------------------------------------------
#define BK 32
#define APITCH 36
#define A_WORDS (128 * APITCH)
#define B_WORDS (64 * APITCH)
#define SMEM_WORDS (2 * (A_WORDS + B_WORDS))

template <int MODE>
__global__ __launch_bounds__(256)
void gemm_tc_kernel(const float* __restrict__ A,
                    const float* __restrict__ W,
                    const float* __restrict__ bias,
                    float* __restrict__ out,
                    int M, int N, int K)
{
    extern __shared__ uint32_t smem[];
    uint32_t* As = smem;
    uint32_t* Bs = smem + 2 * A_WORDS;

    const int tid  = threadIdx.x;
    const int lane = tid & 31;
    const int warp = tid >> 5;
    const int warpM = warp >> 1;
    const int warpN = warp & 1;
    const int g   = lane >> 2;
    const int tig = lane & 3;

    const int bm = blockIdx.y * 128;
    const int bn = blockIdx.x * 64;

    const int lrA = tid >> 1;
    const int lkA = (tid & 1) * 16;
    const int lrB = tid >> 2;
    const int lkB = (tid & 3) * 8;

    const float* Aptr = A + (size_t)(bm + lrA) * K + lkA;
    const float* Wptr = W + (size_t)(bn + lrB) * K + lkB;

    float c[2][4][4];
    #pragma unroll
    for (int mt = 0; mt < 2; mt++)
        #pragma unroll
        for (int nt = 0; nt < 4; nt++)
            #pragma unroll
            for (int i = 0; i < 4; i++) c[mt][nt][i] = 0.0f;

    {
        #pragma unroll
        for (int i = 0; i < 4; i++) {
            float4 v = *(const float4*)(Aptr + i * 4);
            uint4 u = { f2tf32(v.x), f2tf32(v.y), f2tf32(v.z), f2tf32(v.w) };
            *(uint4*)&As[lrA * APITCH + lkA + i * 4] = u;
        }
        #pragma unroll
        for (int i = 0; i < 2; i++) {
            float4 v = *(const float4*)(Wptr + i * 4);
            uint4 u = { f2tf32(v.x), f2tf32(v.y), f2tf32(v.z), f2tf32(v.w) };
            *(uint4*)&Bs[lrB * APITCH + lkB + i * 4] = u;
        }
    }
    __syncthreads();

    int buf = 0;
    const int arow = warpM * 32;
    const int bcol = warpN * 32;

    for (int k0 = BK; k0 <= K; k0 += BK) {
        float4 pa[4], pw[2];
        const bool more = (k0 < K);
        if (more) {
            #pragma unroll
            for (int i = 0; i < 4; i++) pa[i] = *(const float4*)(Aptr + k0 + i * 4);
            #pragma unroll
            for (int i = 0; i < 2; i++) pw[i] = *(const float4*)(Wptr + k0 + i * 4);
        }

        const uint32_t* Ab = As + buf * A_WORDS;
        const uint32_t* Bb = Bs + buf * B_WORDS;
        #pragma unroll
        for (int ks = 0; ks < 4; ks++) {
            const int kc = ks * 8;
            uint32_t afr[2][4], bfr[4][2];
            #pragma unroll
            for (int mt = 0; mt < 2; mt++) {
                const int r0 = arow + mt * 16;
                afr[mt][0] = Ab[(r0 + g)     * APITCH + kc + tig];
                afr[mt][1] = Ab[(r0 + g + 8) * APITCH + kc + tig];
                afr[mt][2] = Ab[(r0 + g)     * APITCH + kc + tig + 4];
                afr[mt][3] = Ab[(r0 + g + 8) * APITCH + kc + tig + 4];
            }
            #pragma unroll
            for (int nt = 0; nt < 4; nt++) {
                const int n = bcol + nt * 8 + g;
                bfr[nt][0] = Bb[n * APITCH + kc + tig];
                bfr[nt][1] = Bb[n * APITCH + kc + tig + 4];
            }
            #pragma unroll
            for (int mt = 0; mt < 2; mt++)
                #pragma unroll
                for (int nt = 0; nt < 4; nt++)
                    mma_tf32(c[mt][nt], afr[mt], bfr[nt]);
        }

        if (more) {
            buf ^= 1;
            uint32_t* Aw = As + buf * A_WORDS;
            uint32_t* Bw = Bs + buf * B_WORDS;
            __syncthreads();
            #pragma unroll
            for (int i = 0; i < 4; i++) {
                uint4 u = { f2tf32(pa[i].x), f2tf32(pa[i].y), f2tf32(pa[i].z), f2tf32(pa[i].w) };
                *(uint4*)&Aw[lrA * APITCH + lkA + i * 4] = u;
            }
            #pragma unroll
            for (int i = 0; i < 2; i++) {
                uint4 u = { f2tf32(pw[i].x), f2tf32(pw[i].y), f2tf32(pw[i].z), f2tf32(pw[i].w) };
                *(uint4*)&Bw[lrB * APITCH + lkB + i * 4] = u;
            }
            __syncthreads();
        }
    }

    #pragma unroll
    for (int mt = 0; mt < 2; mt++) {
        #pragma unroll
        for (int nt = 0; nt < 4; nt++) {
            #pragma unroll
            for (int i = 0; i < 4; i++) {
                const int m = bm + arow + mt * 16 + g + (i >> 1) * 8;
                const int n = bn + bcol + nt * 8 + 2 * tig + (i & 1);
                const float v = c[mt][nt][i] + bias[n];
                if (MODE == 0) {
                    out[(size_t)m * N + n] = v;
                } else {
                    const int bidx = m / S;
                    const int s    = m % S;
                    const int h    = n / DK;
                    const int d    = n % DK;
                    out[(((size_t)bidx * HEADS + h) * S + s) * DK + d] = v;
                }
            }
        }
    }
}

// ---------------------------------------------------------------------------
// Tensor-core flash attention (tf32 mma).
// Block: 128 queries of one (b,h). 8 warps, each owns a 16-row slab.
// KV tiles of 64 keys. Q fragments live in registers for the whole kernel.
// Softmax rows map entirely into one warp -> register + shfl reduction only.
// P staged in warp-private smem slab (syncwarp only), fed back as mma A-op.
// ---------------------------------------------------------------------------
#define KPITCH 52          // K tile pitch (words)  - conflict-free QK B-frags
#define VPITCH 56          // V tile pitch (words)  - conflict-free PV B-frags
#define PPITCH 68          // P/Q tile pitch (words) - conflict-free A-frags
#define ATT_SMEM_WORDS (64 * KPITCH + 64 * VPITCH + 128 * PPITCH)

__global__ __launch_bounds__(256)
void attention_mma_kernel(const float* __restrict__ Q,
                          const float* __restrict__ K,
                          const float* __restrict__ V,
                          float* __restrict__ ctx)
{
    extern __shared__ uint32_t sm[];
    uint32_t* Ks = sm;                                   // [64][KPITCH]
    uint32_t* Vs = sm + 64 * KPITCH;                     // [64][VPITCH]
    uint32_t* Ps = sm + 64 * KPITCH + 64 * VPITCH;       // [128][PPITCH]

    const int qt   = blockIdx.x;      // 0..15
    const int h    = blockIdx.y;
    const int b    = blockIdx.z;
    const int tid  = threadIdx.x;
    const int lane = tid & 31;
    const int warp = tid >> 5;        // 0..7
    const int g    = lane >> 2;       // 0..7
    const int tig  = lane & 3;        // 0..3
    const int r0   = warp * 16;       // warp's query-row base within tile

    const size_t head_off = ((size_t)b * HEADS + h) * S * DK;
    const float scale = rsqrtf((float)DK);

    // ---- stage Q tile (pre-scaled, tf32) into Ps ----
    {
        const float4* qsrc = (const float4*)(Q + head_off + (size_t)qt * 128 * DK);
        #pragma unroll
        for (int i = tid; i < 128 * 12; i += 256) {
            float4 v = qsrc[i];
            const int row = i / 12, c4 = (i % 12) * 4;
            uint32_t* dst = &Ps[row * PPITCH + c4];
            dst[0] = f2tf32(v.x * scale); dst[1] = f2tf32(v.y * scale);
            dst[2] = f2tf32(v.z * scale); dst[3] = f2tf32(v.w * scale);
        }
    }
    __syncthreads();

    // ---- Q fragments -> registers (reused all 32 KV iterations) ----
    uint32_t qf[6][4];
    #pragma unroll
    for (int ks = 0; ks < 6; ks++) {
        const int kc = ks * 8;
        qf[ks][0] = Ps[(r0 + g)     * PPITCH + kc + tig];
        qf[ks][1] = Ps[(r0 + g + 8) * PPITCH + kc + tig];
        qf[ks][2] = Ps[(r0 + g)     * PPITCH + kc + tig + 4];
        qf[ks][3] = Ps[(r0 + g + 8) * PPITCH + kc + tig + 4];
    }

    float ctxa[6][4];                    // running context, 6 n-tiles over dk
    #pragma unroll
    for (int nt = 0; nt < 6; nt++)
        #pragma unroll
        for (int i = 0; i < 4; i++) ctxa[nt][i] = 0.0f;
    float mrun0 = -INFINITY, mrun1 = -INFINITY;
    float lrun0 = 0.0f,      lrun1 = 0.0f;

    const float4* kb = (const float4*)(K + head_off);
    const float4* vb = (const float4*)(V + head_off);

    for (int kt = 0; kt < S / 64; kt++) {
        __syncthreads();     // previous iteration done reading Ks/Vs

        // ---- stage K and V tiles (64x48 each, tf32) ----
        {
            const float4* ksrc = kb + (size_t)kt * 64 * 12;
            const float4* vsrc = vb + (size_t)kt * 64 * 12;
            #pragma unroll
            for (int i = tid; i < 768; i += 256) {
                const int row = i / 12, c4 = (i % 12) * 4;
                float4 kv = ksrc[i];
                uint32_t* kd = &Ks[row * KPITCH + c4];
                kd[0] = f2tf32(kv.x); kd[1] = f2tf32(kv.y);
                kd[2] = f2tf32(kv.z); kd[3] = f2tf32(kv.w);
                float4 vv = vsrc[i];
                uint32_t* vd = &Vs[row * VPITCH + c4];
                vd[0] = f2tf32(vv.x); vd[1] = f2tf32(vv.y);
                vd[2] = f2tf32(vv.z); vd[3] = f2tf32(vv.w);
            }
        }
        __syncthreads();

        // ---- scores = Q @ K^T : c[8 n-tiles][4] on tensor pipe ----
        float sc[8][4];
        #pragma unroll
        for (int nt = 0; nt < 8; nt++)
            #pragma unroll
            for (int i = 0; i < 4; i++) sc[nt][i] = 0.0f;

        #pragma unroll
        for (int ks = 0; ks < 6; ks++) {
            const int kc = ks * 8;
            #pragma unroll
            for (int nt = 0; nt < 8; nt++) {
                uint32_t bfr[2];
                const uint32_t* kr = &Ks[(nt * 8 + g) * KPITCH + kc];
                bfr[0] = kr[tig];
                bfr[1] = kr[tig + 4];
                mma_tf32(sc[nt], qf[ks], bfr);
            }
        }

        // ---- online softmax (register + shfl; rows are warp-local) ----
        float m0 = sc[0][0], m1 = sc[0][2];
        #pragma unroll
        for (int nt = 0; nt < 8; nt++) {
            m0 = fmaxf(m0, fmaxf(sc[nt][0], sc[nt][1]));
            m1 = fmaxf(m1, fmaxf(sc[nt][2], sc[nt][3]));
        }
        m0 = fmaxf(m0, __shfl_xor_sync(0xFFFFFFFF, m0, 1));
        m0 = fmaxf(m0, __shfl_xor_sync(0xFFFFFFFF, m0, 2));
        m1 = fmaxf(m1, __shfl_xor_sync(0xFFFFFFFF, m1, 1));
        m1 = fmaxf(m1, __shfl_xor_sync(0xFFFFFFFF, m1, 2));

        const float mn0 = fmaxf(mrun0, m0);
        const float mn1 = fmaxf(mrun1, m1);
        const float corr0 = __expf(mrun0 - mn0);   // exp(-inf)=0 first time
        const float corr1 = __expf(mrun1 - mn1);
        mrun0 = mn0; mrun1 = mn1;
        lrun0 *= corr0; lrun1 *= corr1;
        #pragma unroll
        for (int nt = 0; nt < 6; nt++) {
            ctxa[nt][0] *= corr0; ctxa[nt][1] *= corr0;
            ctxa[nt][2] *= corr1; ctxa[nt][3] *= corr1;
        }

        // exp + partial row-sums + store P (tf32) into warp-private slab
        #pragma unroll
        for (int nt = 0; nt < 8; nt++) {
            float p0 = __expf(sc[nt][0] - mn0);
            float p1 = __expf(sc[nt][1] - mn0);
            float p2 = __expf(sc[nt][2] - mn1);
            float p3 = __expf(sc[nt][3] - mn1);
            lrun0 += p0 + p1;
            lrun1 += p2 + p3;
            uint2 u01 = { f2tf32(p0), f2tf32(p1) };
            uint2 u23 = { f2tf32(p2), f2tf32(p3) };
            *(uint2*)&Ps[(r0 + g)     * PPITCH + nt * 8 + 2 * tig] = u01;
            *(uint2*)&Ps[(r0 + g + 8) * PPITCH + nt * 8 + 2 * tig] = u23;
        }
        __syncwarp();

        // ---- ctx += P @ V on tensor pipe ----
        #pragma unroll
        for (int ks = 0; ks < 8; ks++) {
            const int kc = ks * 8;
            uint32_t afr[4];
            afr[0] = Ps[(r0 + g)     * PPITCH + kc + tig];
            afr[1] = Ps[(r0 + g + 8) * PPITCH + kc + tig];
            afr[2] = Ps[(r0 + g)     * PPITCH + kc + tig + 4];
            afr[3] = Ps[(r0 + g + 8) * PPITCH + kc + tig + 4];
            #pragma unroll
            for (int nt = 0; nt < 6; nt++) {
                uint32_t bfr[2];
                const uint32_t* vr = &Vs[(kc + tig) * VPITCH + nt * 8 + g];
                bfr[0] = vr[0];
                bfr[1] = vr[4 * VPITCH];
                mma_tf32(ctxa[nt], afr, bfr);
            }
        }
    }

    // ---- epilogue: finish row sums, normalize, write ctx [B,S,DIM] ----
    lrun0 += __shfl_xor_sync(0xFFFFFFFF, lrun0, 1);
    lrun0 += __shfl_xor_sync(0xFFFFFFFF, lrun0, 2);
    lrun1 += __shfl_xor_sync(0xFFFFFFFF, lrun1, 1);
    lrun1 += __shfl_xor_sync(0xFFFFFFFF, lrun1, 2);
    const float inv0 = 1.0f / lrun0;
    const float inv1 = 1.0f / lrun1;

    const int srow0 = qt * 128 + r0 + g;
    float* out0 = ctx + ((size_t)b * S + srow0)     * DIM + h * DK;
    float* out1 = ctx + ((size_t)b * S + srow0 + 8) * DIM + h * DK;
    #pragma unroll
    for (int nt = 0; nt < 6; nt++) {
        const int col = nt * 8 + 2 * tig;
        float2 o0 = { ctxa[nt][0] * inv0, ctxa[nt][1] * inv0 };
        float2 o1 = { ctxa[nt][2] * inv1, ctxa[nt][3] * inv1 };
        *(float2*)(out0 + col) = o0;
        *(float2*)(out1 + col) = o1;
    }
}

// ---------------------------------------------------------------------------
extern "C" void kernel_launch(void* const* d_in, const int* in_sizes, int n_in,
                              void* d_out, int out_size)
{
    const float* x  = (const float*)d_in[0];
    const float* Wq = (const float*)d_in[1];
    const float* bq = (const float*)d_in[2];
    const float* Wk = (const float*)d_in[3];
    const float* bk = (const float*)d_in[4];
    const float* Wv = (const float*)d_in[5];
    const float* bv = (const float*)d_in[6];
    const float* Wo = (const float*)d_in[7];
    const float* bo = (const float*)d_in[8];
    float* out = (float*)d_out;

    float *q, *k, *v, *ctx;
    cudaGetSymbolAddress((void**)&q,   g_q);
    cudaGetSymbolAddress((void**)&k,   g_k);
    cudaGetSymbolAddress((void**)&v,   g_v);
    cudaGetSymbolAddress((void**)&ctx, g_ctx);

    const int gemm_smem = SMEM_WORDS * 4;
    cudaFuncSetAttribute(gemm_tc_kernel<0>,
                         cudaFuncAttributeMaxDynamicSharedMemorySize, gemm_smem);
    cudaFuncSetAttribute(gemm_tc_kernel<1>,
                         cudaFuncAttributeMaxDynamicSharedMemorySize, gemm_smem);
    const int att_smem = ATT_SMEM_WORDS * 4;   // 61952 bytes
    cudaFuncSetAttribute(attention_mma_kernel,
                         cudaFuncAttributeMaxDynamicSharedMemorySize, att_smem);

    dim3 gblk(256);
    dim3 ggrd(DIM / 64, MROWS / 128);   // (12, 32)

    gemm_tc_kernel<1><<<ggrd, gblk, gemm_smem>>>(x, Wq, bq, q, MROWS, DIM, DIM);
    gemm_tc_kernel<1><<<ggrd, gblk, gemm_smem>>>(x, Wk, bk, k, MROWS, DIM, DIM);
    gemm_tc_kernel<1><<<ggrd, gblk, gemm_smem>>>(x, Wv, bv, v, MROWS, DIM, DIM);

    dim3 agrd(S / 128, HEADS, B);       // (16, 16, 2)
    attention_mma_kernel<<<agrd, 256, att_smem>>>(q, k, v, ctx);

    gemm_tc_kernel<0><<<ggrd, gblk, gemm_smem>>>(ctx, Wo, bo, out, MROWS, DIM, DIM);
}